// round 8
// baseline (speedup 1.0000x reference)
#include <cuda_runtime.h>

// CustomSoftmaxExperts, threshold-only form (top-5 condition is vacuous:
// softmax values sum to 1, so any value >= 0.2 has at most 4 values above
// it and is automatically >= the 5th-largest).
//
// Layout: 8 lanes per row, 2 float4 per lane per row, 2 rows per thread.
//  - 4 LDG.128 per thread; each warp load covers exactly 128B x 4 rows
//    = 4 cache lines (minimum wavefronts: 2 wf/row for loads, 2 for stores).
//  - reductions: 3 xor-shuffles (offsets 4,2,1) within the 8-lane group;
//    the two rows form independent chains that interleave.

#define THRESHOLD 0.2f

__global__ __launch_bounds__(256)
void softmax_thresh_kernel(const float4* __restrict__ in,
                           float4* __restrict__ out,
                           int nrows)
{
    const int t   = blockIdx.x * blockDim.x + threadIdx.x;
    const int grp = t >> 3;             // handles rows 2*grp and 2*grp+1
    const int l8  = threadIdx.x & 7;    // lane within 8-lane row group
    if (2 * grp >= nrows) return;

    const unsigned FULL = 0xFFFFFFFFu;

    // Row = 64 floats = 16 float4s. Lane l8 takes float4s {l8, l8+8} of each row.
    const size_t base = (size_t)grp * 32 + l8;   // rows 2g (16) + 2g+1 (16)
    float4 a0 = in[base];        // row0, bytes [l8*16, +16)      of first 128B
    float4 a1 = in[base + 8];    // row0, second 128B
    float4 b0 = in[base + 16];   // row1, first 128B
    float4 b1 = in[base + 24];   // row1, second 128B

    // ---- local max per row (ILP, both rows interleaved) ----
    float ma = fmaxf(fmaxf(fmaxf(a0.x, a0.y), fmaxf(a0.z, a0.w)),
                     fmaxf(fmaxf(a1.x, a1.y), fmaxf(a1.z, a1.w)));
    float mb = fmaxf(fmaxf(fmaxf(b0.x, b0.y), fmaxf(b0.z, b0.w)),
                     fmaxf(fmaxf(b1.x, b1.y), fmaxf(b1.z, b1.w)));

    // ---- row max: 3 shuffles within 8-lane group, two chains interleaved ----
    #pragma unroll
    for (int o = 4; o; o >>= 1) {
        ma = fmaxf(ma, __shfl_xor_sync(FULL, ma, o));
        mb = fmaxf(mb, __shfl_xor_sync(FULL, mb, o));
    }

    // ---- exp (16 independent MUFU ops) ----
    float ea0x = __expf(a0.x - ma), ea0y = __expf(a0.y - ma);
    float ea0z = __expf(a0.z - ma), ea0w = __expf(a0.w - ma);
    float ea1x = __expf(a1.x - ma), ea1y = __expf(a1.y - ma);
    float ea1z = __expf(a1.z - ma), ea1w = __expf(a1.w - ma);
    float eb0x = __expf(b0.x - mb), eb0y = __expf(b0.y - mb);
    float eb0z = __expf(b0.z - mb), eb0w = __expf(b0.w - mb);
    float eb1x = __expf(b1.x - mb), eb1y = __expf(b1.y - mb);
    float eb1z = __expf(b1.z - mb), eb1w = __expf(b1.w - mb);

    float sa = ((ea0x + ea0y) + (ea0z + ea0w)) + ((ea1x + ea1y) + (ea1z + ea1w));
    float sb = ((eb0x + eb0y) + (eb0z + eb0w)) + ((eb1x + eb1y) + (eb1z + eb1w));

    // ---- row sum: 3 shuffles, interleaved chains ----
    #pragma unroll
    for (int o = 4; o; o >>= 1) {
        sa += __shfl_xor_sync(FULL, sa, o);
        sb += __shfl_xor_sync(FULL, sb, o);
    }
    float ia = __frcp_rn(sa);
    float ib = __frcp_rn(sb);

    // ---- softmax + threshold, 4 STG.128 ----
    float4 o4; float v;
    v = ea0x * ia; o4.x = (v >= THRESHOLD) ? v : 0.0f;
    v = ea0y * ia; o4.y = (v >= THRESHOLD) ? v : 0.0f;
    v = ea0z * ia; o4.z = (v >= THRESHOLD) ? v : 0.0f;
    v = ea0w * ia; o4.w = (v >= THRESHOLD) ? v : 0.0f;
    out[base] = o4;

    v = ea1x * ia; o4.x = (v >= THRESHOLD) ? v : 0.0f;
    v = ea1y * ia; o4.y = (v >= THRESHOLD) ? v : 0.0f;
    v = ea1z * ia; o4.z = (v >= THRESHOLD) ? v : 0.0f;
    v = ea1w * ia; o4.w = (v >= THRESHOLD) ? v : 0.0f;
    out[base + 8] = o4;

    v = eb0x * ib; o4.x = (v >= THRESHOLD) ? v : 0.0f;
    v = eb0y * ib; o4.y = (v >= THRESHOLD) ? v : 0.0f;
    v = eb0z * ib; o4.z = (v >= THRESHOLD) ? v : 0.0f;
    v = eb0w * ib; o4.w = (v >= THRESHOLD) ? v : 0.0f;
    out[base + 16] = o4;

    v = eb1x * ib; o4.x = (v >= THRESHOLD) ? v : 0.0f;
    v = eb1y * ib; o4.y = (v >= THRESHOLD) ? v : 0.0f;
    v = eb1z * ib; o4.z = (v >= THRESHOLD) ? v : 0.0f;
    v = eb1w * ib; o4.w = (v >= THRESHOLD) ? v : 0.0f;
    out[base + 24] = o4;
}

extern "C" void kernel_launch(void* const* d_in, const int* in_sizes, int n_in,
                              void* d_out, int out_size)
{
    const float4* in  = (const float4*)d_in[0];
    float4*       out = (float4*)d_out;
    int nrows = in_sizes[0] / 64;      // 262144

    const int threads = 256;           // 64 rows per block (2 per thread)
    int total = nrows * 4;             // 8 lanes/row / 2 rows/thread
    int blocks = (total + threads - 1) / threads;
    softmax_thresh_kernel<<<blocks, threads>>>(in, out, nrows);
}

// round 9
// speedup vs baseline: 1.0762x; 1.0762x over previous
#include <cuda_runtime.h>

// CustomSoftmaxExperts, threshold-only form (top-5 condition is vacuous:
// softmax values sum to 1, so any value >= 0.2 has at most 4 values above
// it and is automatically >= the 5th-largest).
//
// Layout (unchanged from R7): 8 lanes per row, 2 float4 per lane per row,
// 2 rows per thread; 4 LDG.128 per thread, 3-shuffle reductions, two
// independent row chains interleaved.
//
// New this round: stores use __stcs (evict-first streaming). The output is
// dead after writeback while the input is re-read on every graph replay;
// streaming the stores keeps the 64MB input resident in the 126MB L2 so
// replays read mostly from L2, cutting DRAM traffic ~85MB -> ~68MB.

#define THRESHOLD 0.2f

__global__ __launch_bounds__(256)
void softmax_thresh_kernel(const float4* __restrict__ in,
                           float4* __restrict__ out,
                           int nrows)
{
    const int t   = blockIdx.x * blockDim.x + threadIdx.x;
    const int grp = t >> 3;             // handles rows 2*grp and 2*grp+1
    const int l8  = threadIdx.x & 7;    // lane within 8-lane row group
    if (2 * grp >= nrows) return;

    const unsigned FULL = 0xFFFFFFFFu;

    // Row = 64 floats = 16 float4s. Lane l8 takes float4s {l8, l8+8} of each row.
    const size_t base = (size_t)grp * 32 + l8;
    float4 a0 = in[base];        // row0, first 128B
    float4 a1 = in[base + 8];    // row0, second 128B
    float4 b0 = in[base + 16];   // row1, first 128B
    float4 b1 = in[base + 24];   // row1, second 128B

    // ---- local max per row ----
    float ma = fmaxf(fmaxf(fmaxf(a0.x, a0.y), fmaxf(a0.z, a0.w)),
                     fmaxf(fmaxf(a1.x, a1.y), fmaxf(a1.z, a1.w)));
    float mb = fmaxf(fmaxf(fmaxf(b0.x, b0.y), fmaxf(b0.z, b0.w)),
                     fmaxf(fmaxf(b1.x, b1.y), fmaxf(b1.z, b1.w)));

    // ---- row max: 3 shuffles within 8-lane group, interleaved chains ----
    #pragma unroll
    for (int o = 4; o; o >>= 1) {
        ma = fmaxf(ma, __shfl_xor_sync(FULL, ma, o));
        mb = fmaxf(mb, __shfl_xor_sync(FULL, mb, o));
    }

    // ---- exp (16 independent MUFU ops) ----
    float ea0x = __expf(a0.x - ma), ea0y = __expf(a0.y - ma);
    float ea0z = __expf(a0.z - ma), ea0w = __expf(a0.w - ma);
    float ea1x = __expf(a1.x - ma), ea1y = __expf(a1.y - ma);
    float ea1z = __expf(a1.z - ma), ea1w = __expf(a1.w - ma);
    float eb0x = __expf(b0.x - mb), eb0y = __expf(b0.y - mb);
    float eb0z = __expf(b0.z - mb), eb0w = __expf(b0.w - mb);
    float eb1x = __expf(b1.x - mb), eb1y = __expf(b1.y - mb);
    float eb1z = __expf(b1.z - mb), eb1w = __expf(b1.w - mb);

    float sa = ((ea0x + ea0y) + (ea0z + ea0w)) + ((ea1x + ea1y) + (ea1z + ea1w));
    float sb = ((eb0x + eb0y) + (eb0z + eb0w)) + ((eb1x + eb1y) + (eb1z + eb1w));

    // ---- row sum: 3 shuffles, interleaved chains ----
    #pragma unroll
    for (int o = 4; o; o >>= 1) {
        sa += __shfl_xor_sync(FULL, sa, o);
        sb += __shfl_xor_sync(FULL, sb, o);
    }
    float ia = __frcp_rn(sa);
    float ib = __frcp_rn(sb);

    // ---- softmax + threshold, 4 streaming STG.128 ----
    float4 o4; float v;
    v = ea0x * ia; o4.x = (v >= THRESHOLD) ? v : 0.0f;
    v = ea0y * ia; o4.y = (v >= THRESHOLD) ? v : 0.0f;
    v = ea0z * ia; o4.z = (v >= THRESHOLD) ? v : 0.0f;
    v = ea0w * ia; o4.w = (v >= THRESHOLD) ? v : 0.0f;
    __stcs(&out[base], o4);

    v = ea1x * ia; o4.x = (v >= THRESHOLD) ? v : 0.0f;
    v = ea1y * ia; o4.y = (v >= THRESHOLD) ? v : 0.0f;
    v = ea1z * ia; o4.z = (v >= THRESHOLD) ? v : 0.0f;
    v = ea1w * ia; o4.w = (v >= THRESHOLD) ? v : 0.0f;
    __stcs(&out[base + 8], o4);

    v = eb0x * ib; o4.x = (v >= THRESHOLD) ? v : 0.0f;
    v = eb0y * ib; o4.y = (v >= THRESHOLD) ? v : 0.0f;
    v = eb0z * ib; o4.z = (v >= THRESHOLD) ? v : 0.0f;
    v = eb0w * ib; o4.w = (v >= THRESHOLD) ? v : 0.0f;
    __stcs(&out[base + 16], o4);

    v = eb1x * ib; o4.x = (v >= THRESHOLD) ? v : 0.0f;
    v = eb1y * ib; o4.y = (v >= THRESHOLD) ? v : 0.0f;
    v = eb1z * ib; o4.z = (v >= THRESHOLD) ? v : 0.0f;
    v = eb1w * ib; o4.w = (v >= THRESHOLD) ? v : 0.0f;
    __stcs(&out[base + 24], o4);
}

extern "C" void kernel_launch(void* const* d_in, const int* in_sizes, int n_in,
                              void* d_out, int out_size)
{
    const float4* in  = (const float4*)d_in[0];
    float4*       out = (float4*)d_out;
    int nrows = in_sizes[0] / 64;      // 262144

    const int threads = 256;           // 64 rows per block (2 per thread)
    int total = nrows * 4;             // 8 lanes/row, 2 rows/thread
    int blocks = (total + threads - 1) / threads;
    softmax_thresh_kernel<<<blocks, threads>>>(in, out, nrows);
}